// round 12
// baseline (speedup 1.0000x reference)
#include <cuda_runtime.h>
#include <cuda_fp16.h>
#include <cstdint>

#define N_NODES 50000
#define N_EDGES 800000
#define NODE_C  128
#define EDGE_C  64

// ---------------------------------------------------------------------------
// Device scratch (no cudaMalloc allowed)
// ---------------------------------------------------------------------------
__device__ float g_aggr[(size_t)N_NODES * EDGE_C];
__device__ __align__(16) __half g_xn_h[(size_t)N_NODES * NODE_C];
__device__ __align__(16) __half g_eW1t[128 * 320];
__device__ __align__(16) __half g_eW2t[64 * 128];
__device__ __align__(16) __half g_nW1t[128 * 192];
__device__ __align__(16) __half g_nW2t[128 * 128];

// ---------------------------------------------------------------------------
// Helpers
// ---------------------------------------------------------------------------
__device__ __forceinline__ uint32_t smem_u32(const void* p) {
    uint32_t a;
    asm("{ .reg .u64 t; cvta.to.shared.u64 t, %1; cvt.u32.u64 %0, t; }"
        : "=r"(a) : "l"(p));
    return a;
}

// Panels: [rows][64] fp16, 128-byte rows, XOR-swizzled 16B blocks.
__device__ __forceinline__ uint32_t panel_off(uint32_t r, uint32_t k) {
    return r * 128u + ((((k >> 3) ^ (r & 7u)) << 4) | ((k & 7u) << 1));
}

__device__ __forceinline__ void ldsm_x4(uint32_t* d, uint32_t a) {
    asm volatile("ldmatrix.sync.aligned.m8n8.x4.shared.b16 {%0,%1,%2,%3}, [%4];"
                 : "=r"(d[0]), "=r"(d[1]), "=r"(d[2]), "=r"(d[3]) : "r"(a));
}

#define MMA16816(c, a, b) \
    asm volatile("mma.sync.aligned.m16n8k16.row.col.f32.f16.f16.f32 " \
        "{%0,%1,%2,%3},{%4,%5,%6,%7},{%8,%9},{%0,%1,%2,%3};" \
        : "+f"((c)[0]), "+f"((c)[1]), "+f"((c)[2]), "+f"((c)[3]) \
        : "r"((a)[0]), "r"((a)[1]), "r"((a)[2]), "r"((a)[3]), \
          "r"((b)[0]), "r"((b)[1]))

__device__ __forceinline__ void cp16(uint32_t dst, const void* src) {
    asm volatile("cp.async.cg.shared.global [%0], [%1], 16;"
                 :: "r"(dst), "l"(src) : "memory");
}
#define CP_COMMIT() asm volatile("cp.async.commit_group;" ::: "memory")
#define CP_WAIT(n)  asm volatile("cp.async.wait_group %0;" :: "n"(n) : "memory")

__device__ __forceinline__ uint32_t f16x2(float lo, float hi) {
    uint32_t r;
    asm("cvt.rn.f16x2.f32 %0, %1, %2;" : "=r"(r) : "f"(hi), "f"(lo));
    return r;
}
__device__ __forceinline__ float silu_f(float x) {
    return x / (1.0f + __expf(-x));
}
__device__ __forceinline__ uint4 pack8(float4 v0, float4 v1) {
    uint4 r;
    r.x = f16x2(v0.x, v0.y);
    r.y = f16x2(v0.z, v0.w);
    r.z = f16x2(v1.x, v1.y);
    r.w = f16x2(v1.z, v1.w);
    return r;
}

// ---------------------------------------------------------------------------
// Fused prep: zero aggr + fp16 x_nodes + transposed fp16 weights
//   blocks [0, 3125)         : zero g_aggr (float4)
//   blocks [3125, 3125+6250) : xn -> fp16
//   blocks [9375, 9375+160)  : weights
// ---------------------------------------------------------------------------
__global__ void prep_kernel(const float* __restrict__ xn,
                            const float* __restrict__ eW1,
                            const float* __restrict__ eW2,
                            const float* __restrict__ nW1,
                            const float* __restrict__ nW2) {
    int b = blockIdx.x;
    if (b < 3125) {
        size_t i = (size_t)b * 256 + threadIdx.x;
        if (i < (size_t)N_NODES * EDGE_C / 4)
            reinterpret_cast<float4*>(g_aggr)[i] = make_float4(0.f, 0.f, 0.f, 0.f);
    } else if (b < 9375) {
        size_t i = (size_t)(b - 3125) * 256 + threadIdx.x;
        if (i < (size_t)N_NODES * NODE_C / 4) {
            float4 v = reinterpret_cast<const float4*>(xn)[i];
            uint2 h;
            h.x = f16x2(v.x, v.y);
            h.y = f16x2(v.z, v.w);
            reinterpret_cast<uint2*>(g_xn_h)[i] = h;
        }
    } else {
        int i = (b - 9375) * 256 + threadIdx.x;
        if (i < 128 * 320) {
            int n = i / 320, k = i % 320;
            g_eW1t[i] = __float2half_rn(eW1[(size_t)k * 128 + n]);
        }
        if (i < 64 * 128) {
            int n = i / 128, k = i % 128;
            g_eW2t[i] = __float2half_rn(eW2[(size_t)k * 64 + n]);
        }
        if (i < 128 * 192) {
            int n = i / 192, k = i % 192;
            g_nW1t[i] = __float2half_rn(nW1[(size_t)k * 128 + n]);
        }
        if (i < 128 * 128) {
            int n = i / 128, k = i % 128;
            g_nW2t[i] = __float2half_rn(nW2[(size_t)k * 128 + n]);
        }
    }
}

// ---------------------------------------------------------------------------
// Edge kernel: 128 edges / CTA, 256 threads, 8 warps = 4 M-strips x 2 N-strips
// 3-stage cp.async pipeline (A + B triple-buffered). 2 CTAs/SM. SMEM 112KB:
//   A bufs: s*16K (s=0,1,2)           [0..48K)
//   B bufs: 48K + s*16K               [48K..96K)
//   B2 (eW2t): 96K + p*8K             [96K..112K)
//   After GEMM1: h p0@0, p1@16K (A buf0/1)
// ---------------------------------------------------------------------------
#define EDGE_SMEM 114688
#define NODE_SMEM 73728

__global__ __launch_bounds__(256, 2)
void edge_mma_kernel(const float* __restrict__ xe,
                     const void*  __restrict__ eidx,
                     const float* __restrict__ eb1,
                     const float* __restrict__ eb2,
                     float* __restrict__ edges_out)
{
    extern __shared__ __align__(1024) char dsm[];
    __shared__ int s_snd[128], s_rcv[128];

    const int tid  = threadIdx.x;
    const int wid  = tid >> 5;
    const int lane = tid & 31;
    const int mw   = wid & 3;      // 32-row strip
    const int nw   = wid >> 2;     // 64-col strip (GEMM1) / 32-col (GEMM2)
    const int e0   = blockIdx.x * 128;

    const uint32_t sb = smem_u32(dsm);
    const uint32_t la_r  = lane & 15;
    const uint32_t la_kb = (lane >> 4) << 3;
    const uint32_t lb_r  = (lane & 7) | ((lane >> 4) << 3);   // x4 B: (n, n+8) pair
    const uint32_t lb_kb = ((lane >> 3) & 1) << 3;

    // edge indices
    {
        const unsigned* w = reinterpret_cast<const unsigned*>(eidx);
        const bool is64 = ((w[1] | w[3] | w[5] | w[7] | w[9] | w[11] | w[13] | w[15]) == 0u);
        if (tid < 128) {
            size_t e = (size_t)e0 + tid;
            if (is64) {
                const long long* p = reinterpret_cast<const long long*>(eidx);
                s_snd[tid] = (int)p[e];
                s_rcv[tid] = (int)p[(size_t)N_EDGES + e];
            } else {
                const int* p = reinterpret_cast<const int*>(eidx);
                s_snd[tid] = p[e];
                s_rcv[tid] = p[(size_t)N_EDGES + e];
            }
        }
    }
    __syncthreads();

    const int gm = tid >> 1;      // gather row (0..127), 2 threads/row
    const int gh = tid & 1;       // 32-col half of the 64-k chunk
    const int bn = tid >> 1;      // weight row (0..127)
    const int bq = tid & 1;       // 32-k half
    const int my_snd = s_snd[gm];
    const int my_rcv = s_rcv[gm];

    // A source row for chunk c (0..3): snd/snd/rcv/rcv, k-offset (c&1)*64
    // issue_group(c): A chunk c (if c<4) + B chunk c into buffers c%3
#define ISSUE_A(c) do { \
        const __half* _a = g_xn_h + (size_t)((c) < 2 ? my_snd : my_rcv) * NODE_C \
                           + ((c) & 1) * 64 + gh * 32; \
        uint32_t _ad = (uint32_t)(((c) % 3) * 16384); \
        _Pragma("unroll") \
        for (int j = 0; j < 4; j++) \
            cp16(sb + _ad + panel_off((uint32_t)gm, (uint32_t)(gh * 32 + j * 8)), _a + j * 8); \
    } while (0)
#define ISSUE_B(c) do { \
        const __half* _s = g_eW1t + (size_t)bn * 320 + (c) * 64 + bq * 32; \
        uint32_t _bd = 49152u + (uint32_t)(((c) % 3) * 16384); \
        _Pragma("unroll") \
        for (int j = 0; j < 4; j++) \
            cp16(sb + _bd + panel_off((uint32_t)bn, (uint32_t)(bq * 32 + j * 8)), _s + j * 8); \
    } while (0)

    // prologue: groups 0 and 1
    ISSUE_A(0); ISSUE_B(0); CP_COMMIT();
    ISSUE_A(1); ISSUE_B(1); CP_COMMIT();

    float c[2][8][4];
#pragma unroll
    for (int a = 0; a < 2; a++)
#pragma unroll
        for (int b = 0; b < 8; b++)
#pragma unroll
            for (int d = 0; d < 4; d++) c[a][b][d] = 0.f;

    float4 xv[8];   // xe registers, filled at ch==2

    // ---------------- GEMM1: 5 K-chunks of 64, 1 barrier/chunk ----------------
#pragma unroll 1
    for (int ch = 0; ch < 5; ch++) {
        if (ch < 4) CP_WAIT(1); else CP_WAIT(0);   // group ch complete
        __syncthreads();

        if (ch == 0) { ISSUE_A(2); ISSUE_B(2); CP_COMMIT(); }
        else if (ch == 1) { ISSUE_A(3); ISSUE_B(3); CP_COMMIT(); }
        else if (ch == 2) {
            // group 4: B chunk 4 + B2 weights; xe -> registers
            ISSUE_B(4);
            {
                const int n2 = tid >> 2;
                const int q2 = tid & 3;
                const __half* s = g_eW2t + (size_t)n2 * 128;
#pragma unroll
                for (int j = 0; j < 4; j++) {
                    int seg = q2 * 4 + j;
                    uint32_t p = (uint32_t)(seg >> 3);
                    uint32_t off = p * 8192u + panel_off((uint32_t)n2, (uint32_t)((seg & 7) * 8));
                    cp16(sb + 98304u + off, s + seg * 8);
                }
            }
            CP_COMMIT();
            const float4* rp = reinterpret_cast<const float4*>(xe + (size_t)(e0 + gm) * EDGE_C) + gh * 8;
#pragma unroll
            for (int i = 0; i < 8; i++) xv[i] = rp[i];
        } else if (ch == 3) {
            // store packed xe into A buf (4%3 = 1); safe: MMA(1) finished long ago
#pragma unroll
            for (int i = 0; i < 4; i++) {
                uint32_t off = 16384u + panel_off((uint32_t)gm, (uint32_t)(gh * 32 + i * 8));
                *(uint4*)(dsm + off) = pack8(xv[2 * i], xv[2 * i + 1]);
            }
        }

        const uint32_t Ap = sb + (uint32_t)((ch % 3) * 16384);
        const uint32_t Bp = sb + 49152u + (uint32_t)((ch % 3) * 16384);
#pragma unroll
        for (int ks = 0; ks < 4; ks++) {
            const uint32_t kb = ks * 16;
            uint32_t a4[2][4];
#pragma unroll
            for (int mf = 0; mf < 2; mf++) {
                uint32_t r = (uint32_t)(mw * 32 + mf * 16) + la_r;
                ldsm_x4(a4[mf], Ap + panel_off(r, kb + la_kb));
            }
#pragma unroll
            for (int np = 0; np < 4; np++) {   // 4 n-frag pairs = 64 cols
                uint32_t n = (uint32_t)(nw * 64 + np * 16) + lb_r;
                uint32_t b4[4];
                ldsm_x4(b4, Bp + panel_off(n, kb + lb_kb));
#pragma unroll
                for (int mf = 0; mf < 2; mf++) {
                    MMA16816(c[mf][np * 2],     a4[mf], b4);
                    MMA16816(c[mf][np * 2 + 1], a4[mf], b4 + 2);
                }
            }
        }
    }
    // NOTE: MMA(4) read A from buf1 (the STS'd xe) — visible via ch=4 barrier.
    __syncthreads();

    // ------------- Epilogue1: bias + SiLU -> h fp16 panels (A buf0/1) -------------
    {
        const int l4 = lane >> 2;
        const int l2 = (lane & 3) * 2;
        const uint32_t hb = (uint32_t)nw * 16384u;   // p0@0, p1@16K
#pragma unroll
        for (int nf = 0; nf < 8; nf++) {
            int col = nw * 64 + nf * 8 + l2;
            float b0 = __ldg(eb1 + col), b1 = __ldg(eb1 + col + 1);
            uint32_t kk = (uint32_t)(nf * 8 + l2);
#pragma unroll
            for (int mf = 0; mf < 2; mf++) {
                uint32_t m = (uint32_t)(mw * 32 + mf * 16 + l4);
                float x0 = silu_f(c[mf][nf][0] + b0);
                float x1 = silu_f(c[mf][nf][1] + b1);
                float x2 = silu_f(c[mf][nf][2] + b0);
                float x3 = silu_f(c[mf][nf][3] + b1);
                *(uint32_t*)(dsm + hb + panel_off(m, kk))     = f16x2(x0, x1);
                *(uint32_t*)(dsm + hb + panel_off(m + 8, kk)) = f16x2(x2, x3);
            }
        }
    }
    __syncthreads();

    // ---------------- GEMM2: h[128,128] @ eW2t^T -> [128,64] ----------------
    float c2[2][4][4];
#pragma unroll
    for (int a = 0; a < 2; a++)
#pragma unroll
        for (int b = 0; b < 4; b++)
#pragma unroll
            for (int d = 0; d < 4; d++) c2[a][b][d] = 0.f;

#pragma unroll
    for (int p = 0; p < 2; p++) {
        const uint32_t Ap = sb + (uint32_t)p * 16384u;
        const uint32_t Bp = sb + 98304u + (uint32_t)p * 8192u;
#pragma unroll
        for (int ks = 0; ks < 4; ks++) {
            const uint32_t kb = ks * 16;
            uint32_t a4[2][4];
#pragma unroll
            for (int mf = 0; mf < 2; mf++) {
                uint32_t r = (uint32_t)(mw * 32 + mf * 16) + la_r;
                ldsm_x4(a4[mf], Ap + panel_off(r, kb + la_kb));
            }
#pragma unroll
            for (int np = 0; np < 2; np++) {   // 2 n-frag pairs = 32 cols
                uint32_t n = (uint32_t)(nw * 32 + np * 16) + lb_r;
                uint32_t b4[4];
                ldsm_x4(b4, Bp + panel_off(n, kb + lb_kb));
#pragma unroll
                for (int mf = 0; mf < 2; mf++) {
                    MMA16816(c2[mf][np * 2],     a4[mf], b4);
                    MMA16816(c2[mf][np * 2 + 1], a4[mf], b4 + 2);
                }
            }
        }
    }

    // ------------- Epilogue2: SiLU, float2 stores, scalar atomics -------------
    {
        const int l4 = lane >> 2;
        const int l2 = (lane & 3) * 2;
        float b0[4], b1[4];
#pragma unroll
        for (int nf = 0; nf < 4; nf++) {
            int col = nw * 32 + nf * 8 + l2;
            b0[nf] = __ldg(eb2 + col);
            b1[nf] = __ldg(eb2 + col + 1);
        }
#pragma unroll
        for (int mf = 0; mf < 2; mf++) {
#pragma unroll
            for (int half = 0; half < 2; half++) {
                int m = mw * 32 + mf * 16 + l4 + half * 8;
                int rcv = s_rcv[m];
                float* orow = edges_out + (size_t)(e0 + m) * EDGE_C;
                float* arow = g_aggr + (size_t)rcv * EDGE_C;
#pragma unroll
                for (int nf = 0; nf < 4; nf++) {
                    int col = nw * 32 + nf * 8 + l2;
                    float o0 = silu_f(c2[mf][nf][half * 2]     + b0[nf]);
                    float o1 = silu_f(c2[mf][nf][half * 2 + 1] + b1[nf]);
                    float2 ov = {o0, o1};
                    *reinterpret_cast<float2*>(orow + col) = ov;
                    atomicAdd(arow + col,     o0);
                    atomicAdd(arow + col + 1, o1);
                }
            }
        }
    }
#undef ISSUE_A
#undef ISSUE_B
}

// ---------------------------------------------------------------------------
// Node kernel: 64 nodes / CTA, 256 threads, 2 CTAs/SM (R11 verbatim)
// ---------------------------------------------------------------------------
__global__ __launch_bounds__(256, 2)
void node_mma_kernel(const float* __restrict__ xn,
                     const float* __restrict__ nb1,
                     const float* __restrict__ nb2,
                     float* __restrict__ nodes_out)
{
    extern __shared__ __align__(1024) char dsm[];

    const int tid  = threadIdx.x;
    const int wid  = tid >> 5;
    const int lane = tid & 31;
    const int mw   = wid & 1;
    const int nw   = wid >> 1;
    const int m0   = blockIdx.x * 64;

    const uint32_t sb = smem_u32(dsm);
    const uint32_t la_r  = lane & 15;
    const uint32_t la_kb = (lane >> 4) << 3;
    const uint32_t lb_r  = (lane & 7) | ((lane >> 4) << 3);
    const uint32_t lb_kb = ((lane >> 3) & 1) << 3;

    const int gm = tid >> 2;
    const int gq = tid & 3;
    const int bn = tid >> 1;
    const int bq = tid & 1;
    const size_t grow = (size_t)m0 + gm;
    const bool gvalid = grow < N_NODES;

    {
        const __half* s = g_nW1t + (size_t)bn * 192 + bq * 32;
#pragma unroll
        for (int j = 0; j < 4; j++) {
            uint32_t off = panel_off((uint32_t)bn, (uint32_t)(bq * 32 + j * 8));
            cp16(sb + 8192u + off, s + j * 8);
        }
        CP_COMMIT();
    }
    float4 av[4];
    {
        const float4* rp = reinterpret_cast<const float4*>(xn + grow * NODE_C) + gq * 4;
#pragma unroll
        for (int i = 0; i < 4; i++)
            av[i] = gvalid ? rp[i] : make_float4(0.f, 0.f, 0.f, 0.f);
    }

    float c[2][4][4];
#pragma unroll
    for (int a = 0; a < 2; a++)
#pragma unroll
        for (int b = 0; b < 4; b++)
#pragma unroll
            for (int d = 0; d < 4; d++) c[a][b][d] = 0.f;

#pragma unroll 1
    for (int ch = 0; ch < 3; ch++) {
        __syncthreads();
#pragma unroll
        for (int i = 0; i < 2; i++) {
            uint32_t off = panel_off((uint32_t)gm, (uint32_t)(gq * 16 + i * 8));
            *(uint4*)(dsm + off) = pack8(av[2 * i], av[2 * i + 1]);
        }
        if (ch < 2) {
            const int nc = ch + 1;
            uint32_t dst = 8192u + (uint32_t)((nc & 1) * 16384);
            const __half* s = g_nW1t + (size_t)bn * 192 + nc * 64 + bq * 32;
#pragma unroll
            for (int j = 0; j < 4; j++) {
                uint32_t off = panel_off((uint32_t)bn, (uint32_t)(bq * 32 + j * 8));
                cp16(sb + dst + off, s + j * 8);
            }
            CP_COMMIT();
            const float* rowp = (nc < 2) ? xn + grow * NODE_C + nc * 64
                                         : g_aggr + grow * EDGE_C;
            const float4* rp = reinterpret_cast<const float4*>(rowp) + gq * 4;
#pragma unroll
            for (int i = 0; i < 4; i++)
                av[i] = gvalid ? rp[i] : make_float4(0.f, 0.f, 0.f, 0.f);
        } else {
            // prefetch B2 (nW2t 128x128): p0@40K p1@56K
            const __half* s = g_nW2t + (size_t)bn * 128;
#pragma unroll
            for (int j = 0; j < 8; j++) {
                int seg = bq * 8 + j;
                uint32_t p = (uint32_t)(seg >> 3);
                uint32_t off = p * 16384u + panel_off((uint32_t)bn, (uint32_t)((seg & 7) * 8));
                cp16(sb + 40960u + off, s + seg * 8);
            }
            CP_COMMIT();
        }
        CP_WAIT(1);
        __syncthreads();

        const uint32_t Bp = sb + 8192u + (uint32_t)((ch & 1) * 16384);
#pragma unroll
        for (int ks = 0; ks < 4; ks++) {
            const uint32_t kb = ks * 16;
            uint32_t a4[2][4];
#pragma unroll
            for (int mf = 0; mf < 2; mf++) {
                uint32_t r = (uint32_t)(mw * 32 + mf * 16) + la_r;
                ldsm_x4(a4[mf], sb + panel_off(r, kb + la_kb));
            }
#pragma unroll
            for (int np = 0; np < 2; np++) {
                uint32_t n = (uint32_t)(nw * 32 + np * 16) + lb_r;
                uint32_t b4[4];
                ldsm_x4(b4, Bp + panel_off(n, kb + lb_kb));
#pragma unroll
                for (int mf = 0; mf < 2; mf++) {
                    MMA16816(c[mf][np * 2],     a4[mf], b4);
                    MMA16816(c[mf][np * 2 + 1], a4[mf], b4 + 2);
                }
            }
        }
    }
    __syncthreads();

    // Epilogue1: bias + SiLU -> h fp16
    {
        const int l4 = lane >> 2;
        const int l2 = (lane & 3) * 2;
        const uint32_t hb = (uint32_t)(nw >> 1) * 8192u;   // p0@0, p1@8K
#pragma unroll
        for (int nf = 0; nf < 4; nf++) {
            int col = nw * 32 + nf * 8 + l2;
            float b0 = __ldg(nb1 + col), b1 = __ldg(nb1 + col + 1);
            uint32_t kk = (uint32_t)((nw & 1) * 32 + nf * 8 + l2);
#pragma unroll
            for (int mf = 0; mf < 2; mf++) {
                uint32_t m = (uint32_t)(mw * 32 + mf * 16 + l4);
                float x0 = silu_f(c[mf][nf][0] + b0);
                float x1 = silu_f(c[mf][nf][1] + b1);
                float x2 = silu_f(c[mf][nf][2] + b0);
                float x3 = silu_f(c[mf][nf][3] + b1);
                *(uint32_t*)(dsm + hb + panel_off(m, kk))     = f16x2(x0, x1);
                *(uint32_t*)(dsm + hb + panel_off(m + 8, kk)) = f16x2(x2, x3);
            }
        }
    }
    CP_WAIT(0);
    __syncthreads();

    // GEMM2: h[64,128] @ nW2t^T -> [64,128]
    float c2[2][4][4];
#pragma unroll
    for (int a = 0; a < 2; a++)
#pragma unroll
        for (int b = 0; b < 4; b++)
#pragma unroll
            for (int d = 0; d < 4; d++) c2[a][b][d] = 0.f;

#pragma unroll
    for (int p = 0; p < 2; p++) {
        const uint32_t Ap = sb + (uint32_t)p * 8192u;
        const uint32_t Bp = sb + 40960u + (uint32_t)p * 16384u;
#pragma unroll
        for (int ks = 0; ks < 4; ks++) {
            const uint32_t kb = ks * 16;
            uint32_t a4[2][4];
#pragma unroll
            for (int mf = 0; mf < 2; mf++) {
                uint32_t r = (uint32_t)(mw * 32 + mf * 16) + la_r;
                ldsm_x4(a4[mf], Ap + panel_off(r, kb + la_kb));
            }
#pragma unroll
            for (int np = 0; np < 2; np++) {
                uint32_t n = (uint32_t)(nw * 32 + np * 16) + lb_r;
                uint32_t b4[4];
                ldsm_x4(b4, Bp + panel_off(n, kb + lb_kb));
#pragma unroll
                for (int mf = 0; mf < 2; mf++) {
                    MMA16816(c2[mf][np * 2],     a4[mf], b4);
                    MMA16816(c2[mf][np * 2 + 1], a4[mf], b4 + 2);
                }
            }
        }
    }

    // Epilogue2: + bias, store
    {
        const int l4 = lane >> 2;
        const int l2 = (lane & 3) * 2;
        float b0[4], b1[4];
#pragma unroll
        for (int nf = 0; nf < 4; nf++) {
            int col = nw * 32 + nf * 8 + l2;
            b0[nf] = __ldg(nb2 + col);
            b1[nf] = __ldg(nb2 + col + 1);
        }
#pragma unroll
        for (int mf = 0; mf < 2; mf++) {
#pragma unroll
            for (int half = 0; half < 2; half++) {
                size_t row = (size_t)m0 + mw * 32 + mf * 16 + l4 + half * 8;
                if (row < N_NODES) {
                    float* orow = nodes_out + row * NODE_C;
#pragma unroll
                    for (int nf = 0; nf < 4; nf++) {
                        int col = nw * 32 + nf * 8 + l2;
                        float2 ov;
                        ov.x = c2[mf][nf][half * 2]     + b0[nf];
                        ov.y = c2[mf][nf][half * 2 + 1] + b1[nf];
                        *reinterpret_cast<float2*>(orow + col) = ov;
                    }
                }
            }
        }
    }
}

// ---------------------------------------------------------------------------
extern "C" void kernel_launch(void* const* d_in, const int* in_sizes, int n_in,
                              void* d_out, int out_size)
{
    const float* xn   = (const float*)d_in[0];
    const float* xe   = (const float*)d_in[1];
    const void*  eidx =               d_in[2];
    const float* eW1  = (const float*)d_in[3];
    const float* eb1  = (const float*)d_in[4];
    const float* eW2  = (const float*)d_in[5];
    const float* eb2  = (const float*)d_in[6];
    const float* nW1  = (const float*)d_in[7];
    const float* nb1  = (const float*)d_in[8];
    const float* nW2  = (const float*)d_in[9];
    const float* nb2  = (const float*)d_in[10];

    float* nodes_out = (float*)d_out;
    float* edges_out = (float*)d_out + (size_t)N_NODES * NODE_C;

    cudaFuncSetAttribute(edge_mma_kernel, cudaFuncAttributeMaxDynamicSharedMemorySize, EDGE_SMEM);
    cudaFuncSetAttribute(node_mma_kernel, cudaFuncAttributeMaxDynamicSharedMemorySize, NODE_SMEM);

    prep_kernel<<<9535, 256>>>(xn, eW1, eW2, nW1, nW2);
    edge_mma_kernel<<<N_EDGES / 128, 256, EDGE_SMEM>>>(xe, eidx, eb1, eb2, edges_out);
    node_mma_kernel<<<(N_NODES + 63) / 64, 256, NODE_SMEM>>>(xn, nb1, nb2, nodes_out);
}

// round 13
// speedup vs baseline: 1.0615x; 1.0615x over previous
#include <cuda_runtime.h>
#include <cuda_fp16.h>
#include <cstdint>

#define N_NODES 50000
#define N_EDGES 800000
#define NODE_C  128
#define EDGE_C  64

// ---------------------------------------------------------------------------
// Device scratch (no cudaMalloc allowed)
// ---------------------------------------------------------------------------
__device__ float g_aggr[(size_t)N_NODES * EDGE_C];
__device__ __align__(16) __half g_xn_h[(size_t)N_NODES * NODE_C];
__device__ __align__(16) __half g_eW1t[128 * 320];
__device__ __align__(16) __half g_eW2t[64 * 128];
__device__ __align__(16) __half g_nW1t[128 * 192];
__device__ __align__(16) __half g_nW2t[128 * 128];

// ---------------------------------------------------------------------------
// Helpers
// ---------------------------------------------------------------------------
__device__ __forceinline__ uint32_t smem_u32(const void* p) {
    uint32_t a;
    asm("{ .reg .u64 t; cvta.to.shared.u64 t, %1; cvt.u32.u64 %0, t; }"
        : "=r"(a) : "l"(p));
    return a;
}

// Panels: [rows][64] fp16, 128-byte rows, XOR-swizzled 16B blocks.
__device__ __forceinline__ uint32_t panel_off(uint32_t r, uint32_t k) {
    return r * 128u + ((((k >> 3) ^ (r & 7u)) << 4) | ((k & 7u) << 1));
}

__device__ __forceinline__ void ldsm_x4(uint32_t* d, uint32_t a) {
    asm volatile("ldmatrix.sync.aligned.m8n8.x4.shared.b16 {%0,%1,%2,%3}, [%4];"
                 : "=r"(d[0]), "=r"(d[1]), "=r"(d[2]), "=r"(d[3]) : "r"(a));
}

#define MMA16816(c, a, b) \
    asm volatile("mma.sync.aligned.m16n8k16.row.col.f32.f16.f16.f32 " \
        "{%0,%1,%2,%3},{%4,%5,%6,%7},{%8,%9},{%0,%1,%2,%3};" \
        : "+f"((c)[0]), "+f"((c)[1]), "+f"((c)[2]), "+f"((c)[3]) \
        : "r"((a)[0]), "r"((a)[1]), "r"((a)[2]), "r"((a)[3]), \
          "r"((b)[0]), "r"((b)[1]))

__device__ __forceinline__ void cp16(uint32_t dst, const void* src) {
    asm volatile("cp.async.cg.shared.global [%0], [%1], 16;"
                 :: "r"(dst), "l"(src) : "memory");
}
#define CP_COMMIT() asm volatile("cp.async.commit_group;" ::: "memory")
#define CP_WAIT(n)  asm volatile("cp.async.wait_group %0;" :: "n"(n) : "memory")

__device__ __forceinline__ uint32_t f16x2(float lo, float hi) {
    uint32_t r;
    asm("cvt.rn.f16x2.f32 %0, %1, %2;" : "=r"(r) : "f"(hi), "f"(lo));
    return r;
}
__device__ __forceinline__ float silu_f(float x) {
    return x / (1.0f + __expf(-x));
}
__device__ __forceinline__ uint4 pack8(float4 v0, float4 v1) {
    uint4 r;
    r.x = f16x2(v0.x, v0.y);
    r.y = f16x2(v0.z, v0.w);
    r.z = f16x2(v1.x, v1.y);
    r.w = f16x2(v1.z, v1.w);
    return r;
}

// ---------------------------------------------------------------------------
// Fused prep: zero aggr + fp16 x_nodes + transposed fp16 weights (from R12)
// ---------------------------------------------------------------------------
__global__ void prep_kernel(const float* __restrict__ xn,
                            const float* __restrict__ eW1,
                            const float* __restrict__ eW2,
                            const float* __restrict__ nW1,
                            const float* __restrict__ nW2) {
    int b = blockIdx.x;
    if (b < 3125) {
        size_t i = (size_t)b * 256 + threadIdx.x;
        if (i < (size_t)N_NODES * EDGE_C / 4)
            reinterpret_cast<float4*>(g_aggr)[i] = make_float4(0.f, 0.f, 0.f, 0.f);
    } else if (b < 9375) {
        size_t i = (size_t)(b - 3125) * 256 + threadIdx.x;
        if (i < (size_t)N_NODES * NODE_C / 4) {
            float4 v = reinterpret_cast<const float4*>(xn)[i];
            uint2 h;
            h.x = f16x2(v.x, v.y);
            h.y = f16x2(v.z, v.w);
            reinterpret_cast<uint2*>(g_xn_h)[i] = h;
        }
    } else {
        int i = (b - 9375) * 256 + threadIdx.x;
        if (i < 128 * 320) {
            int n = i / 320, k = i % 320;
            g_eW1t[i] = __float2half_rn(eW1[(size_t)k * 128 + n]);
        }
        if (i < 64 * 128) {
            int n = i / 128, k = i % 128;
            g_eW2t[i] = __float2half_rn(eW2[(size_t)k * 64 + n]);
        }
        if (i < 128 * 192) {
            int n = i / 192, k = i % 192;
            g_nW1t[i] = __float2half_rn(nW1[(size_t)k * 128 + n]);
        }
        if (i < 128 * 128) {
            int n = i / 128, k = i % 128;
            g_nW2t[i] = __float2half_rn(nW2[(size_t)k * 128 + n]);
        }
    }
}

// ---------------------------------------------------------------------------
// Edge kernel (R11 verbatim): 128 edges / CTA, 256 threads,
// 8 warps = 4 M-strips x 2 N-strips. Double-buffered cp.async. 2 CTAs/SM.
// SMEM 80KB: A buf0@0, buf1@16K; B buf0@32K, buf1@48K; B2 p0@64K p1@72K
// ---------------------------------------------------------------------------
#define EDGE_SMEM 81920
#define NODE_SMEM 73728

__global__ __launch_bounds__(256, 2)
void edge_mma_kernel(const float* __restrict__ xe,
                     const void*  __restrict__ eidx,
                     const float* __restrict__ eb1,
                     const float* __restrict__ eb2,
                     float* __restrict__ edges_out)
{
    extern __shared__ __align__(1024) char dsm[];
    __shared__ int s_snd[128], s_rcv[128];

    const int tid  = threadIdx.x;
    const int wid  = tid >> 5;
    const int lane = tid & 31;
    const int mw   = wid & 3;      // 32-row strip
    const int nw   = wid >> 2;     // 64-col strip (GEMM1) / 32-col (GEMM2)
    const int e0   = blockIdx.x * 128;

    const uint32_t sb = smem_u32(dsm);
    const uint32_t la_r  = lane & 15;
    const uint32_t la_kb = (lane >> 4) << 3;
    const uint32_t lb_r  = (lane & 7) | ((lane >> 4) << 3);   // x4 B: (n, n+8) pair
    const uint32_t lb_kb = ((lane >> 3) & 1) << 3;

    // edge indices
    {
        const unsigned* w = reinterpret_cast<const unsigned*>(eidx);
        const bool is64 = ((w[1] | w[3] | w[5] | w[7] | w[9] | w[11] | w[13] | w[15]) == 0u);
        if (tid < 128) {
            size_t e = (size_t)e0 + tid;
            if (is64) {
                const long long* p = reinterpret_cast<const long long*>(eidx);
                s_snd[tid] = (int)p[e];
                s_rcv[tid] = (int)p[(size_t)N_EDGES + e];
            } else {
                const int* p = reinterpret_cast<const int*>(eidx);
                s_snd[tid] = p[e];
                s_rcv[tid] = p[(size_t)N_EDGES + e];
            }
        }
    }
    __syncthreads();

    const int gm = tid >> 1;      // gather row (0..127), 2 threads/row
    const int gh = tid & 1;       // 32-half piece of the 64-k chunk
    const int bn = tid >> 1;      // weight row (0..127)
    const int bq = tid & 1;       // 32-k half
    const int my_snd = s_snd[gm];
    const int my_rcv = s_rcv[gm];

    // issue group 0 (A0 + B0)
    {
        const __half* s = g_eW1t + (size_t)bn * 320 + bq * 32;
#pragma unroll
        for (int j = 0; j < 4; j++)
            cp16(sb + 32768u + panel_off((uint32_t)bn, (uint32_t)(bq * 32 + j * 8)), s + j * 8);
        const __half* a = g_xn_h + (size_t)my_snd * NODE_C + gh * 32;
#pragma unroll
        for (int j = 0; j < 4; j++)
            cp16(sb + panel_off((uint32_t)gm, (uint32_t)(gh * 32 + j * 8)), a + j * 8);
        CP_COMMIT();
    }

    float c[2][8][4];
#pragma unroll
    for (int a = 0; a < 2; a++)
#pragma unroll
        for (int b = 0; b < 8; b++)
#pragma unroll
            for (int d = 0; d < 4; d++) c[a][b][d] = 0.f;

    float4 xv[8];   // xe registers, filled during ch==3

    // ---------------- GEMM1: 5 K-chunks of 64 ----------------
#pragma unroll 1
    for (int ch = 0; ch < 5; ch++) {
        __syncthreads();   // consumers of the buffer about to be written are done
        if (ch < 3) {
            const int nc = ch + 1;
            const __half* s = g_eW1t + (size_t)bn * 320 + nc * 64 + bq * 32;
            uint32_t bdst = 32768u + (uint32_t)((nc & 1) * 16384);
#pragma unroll
            for (int j = 0; j < 4; j++)
                cp16(sb + bdst + panel_off((uint32_t)bn, (uint32_t)(bq * 32 + j * 8)), s + j * 8);
            const __half* a = g_xn_h + (size_t)(nc < 2 ? my_snd : my_rcv) * NODE_C
                              + (nc & 1) * 64 + gh * 32;
            uint32_t adst = (uint32_t)((nc & 1) * 16384);
#pragma unroll
            for (int j = 0; j < 4; j++)
                cp16(sb + adst + panel_off((uint32_t)gm, (uint32_t)(gh * 32 + j * 8)), a + j * 8);
            CP_COMMIT();
        } else if (ch == 3) {
            // group 4: B only (chunk 4); xe loaded into registers
            const __half* s = g_eW1t + (size_t)bn * 320 + 4 * 64 + bq * 32;
#pragma unroll
            for (int j = 0; j < 4; j++)
                cp16(sb + 32768u + panel_off((uint32_t)bn, (uint32_t)(bq * 32 + j * 8)), s + j * 8);
            CP_COMMIT();
            const float4* rp = reinterpret_cast<const float4*>(xe + (size_t)(e0 + gm) * EDGE_C) + gh * 8;
#pragma unroll
            for (int i = 0; i < 8; i++) xv[i] = rp[i];
        } else {
            // ch == 4: store packed xe into A buf0; prefetch B2 (group 5)
#pragma unroll
            for (int i = 0; i < 4; i++) {
                uint32_t off = panel_off((uint32_t)gm, (uint32_t)(gh * 32 + i * 8));
                *(uint4*)(dsm + off) = pack8(xv[2 * i], xv[2 * i + 1]);
            }
            const int n2 = tid >> 2;
            const int q2 = tid & 3;
            const __half* s = g_eW2t + (size_t)n2 * 128;
#pragma unroll
            for (int j = 0; j < 4; j++) {
                int seg = q2 * 4 + j;
                uint32_t p = (uint32_t)(seg >> 3);
                uint32_t off = p * 8192u + panel_off((uint32_t)n2, (uint32_t)((seg & 7) * 8));
                cp16(sb + 65536u + off, s + seg * 8);
            }
            CP_COMMIT();
        }
        CP_WAIT(1);
        __syncthreads();

        const uint32_t Ap = sb + (uint32_t)((ch & 1) * 16384);
        const uint32_t Bp = sb + 32768u + (uint32_t)((ch & 1) * 16384);
#pragma unroll
        for (int ks = 0; ks < 4; ks++) {
            const uint32_t kb = ks * 16;
            uint32_t a4[2][4];
#pragma unroll
            for (int mf = 0; mf < 2; mf++) {
                uint32_t r = (uint32_t)(mw * 32 + mf * 16) + la_r;
                ldsm_x4(a4[mf], Ap + panel_off(r, kb + la_kb));
            }
#pragma unroll
            for (int np = 0; np < 4; np++) {   // 4 n-frag pairs = 64 cols
                uint32_t n = (uint32_t)(nw * 64 + np * 16) + lb_r;
                uint32_t b4[4];
                ldsm_x4(b4, Bp + panel_off(n, kb + lb_kb));
#pragma unroll
                for (int mf = 0; mf < 2; mf++) {
                    MMA16816(c[mf][np * 2],     a4[mf], b4);
                    MMA16816(c[mf][np * 2 + 1], a4[mf], b4 + 2);
                }
            }
        }
    }
    __syncthreads();

    // ------------- Epilogue1: bias + SiLU -> h fp16 panels (A buffers) -------------
    {
        const int l4 = lane >> 2;
        const int l2 = (lane & 3) * 2;
        const uint32_t hb = (uint32_t)nw * 16384u;   // p0@0, p1@16K
#pragma unroll
        for (int nf = 0; nf < 8; nf++) {
            int col = nw * 64 + nf * 8 + l2;
            float b0 = __ldg(eb1 + col), b1 = __ldg(eb1 + col + 1);
            uint32_t kk = (uint32_t)(nf * 8 + l2);
#pragma unroll
            for (int mf = 0; mf < 2; mf++) {
                uint32_t m = (uint32_t)(mw * 32 + mf * 16 + l4);
                float x0 = silu_f(c[mf][nf][0] + b0);
                float x1 = silu_f(c[mf][nf][1] + b1);
                float x2 = silu_f(c[mf][nf][2] + b0);
                float x3 = silu_f(c[mf][nf][3] + b1);
                *(uint32_t*)(dsm + hb + panel_off(m, kk))     = f16x2(x0, x1);
                *(uint32_t*)(dsm + hb + panel_off(m + 8, kk)) = f16x2(x2, x3);
            }
        }
    }
    CP_WAIT(0);
    __syncthreads();

    // ---------------- GEMM2: h[128,128] @ eW2t^T -> [128,64] ----------------
    float c2[2][4][4];
#pragma unroll
    for (int a = 0; a < 2; a++)
#pragma unroll
        for (int b = 0; b < 4; b++)
#pragma unroll
            for (int d = 0; d < 4; d++) c2[a][b][d] = 0.f;

#pragma unroll
    for (int p = 0; p < 2; p++) {
        const uint32_t Ap = sb + (uint32_t)p * 16384u;
        const uint32_t Bp = sb + 65536u + (uint32_t)p * 8192u;
#pragma unroll
        for (int ks = 0; ks < 4; ks++) {
            const uint32_t kb = ks * 16;
            uint32_t a4[2][4];
#pragma unroll
            for (int mf = 0; mf < 2; mf++) {
                uint32_t r = (uint32_t)(mw * 32 + mf * 16) + la_r;
                ldsm_x4(a4[mf], Ap + panel_off(r, kb + la_kb));
            }
#pragma unroll
            for (int np = 0; np < 2; np++) {   // 2 n-frag pairs = 32 cols
                uint32_t n = (uint32_t)(nw * 32 + np * 16) + lb_r;
                uint32_t b4[4];
                ldsm_x4(b4, Bp + panel_off(n, kb + lb_kb));
#pragma unroll
                for (int mf = 0; mf < 2; mf++) {
                    MMA16816(c2[mf][np * 2],     a4[mf], b4);
                    MMA16816(c2[mf][np * 2 + 1], a4[mf], b4 + 2);
                }
            }
        }
    }

    // ------------- Epilogue2: SiLU, float2 stores, scalar atomics -------------
    {
        const int l4 = lane >> 2;
        const int l2 = (lane & 3) * 2;
        float b0[4], b1[4];
#pragma unroll
        for (int nf = 0; nf < 4; nf++) {
            int col = nw * 32 + nf * 8 + l2;
            b0[nf] = __ldg(eb2 + col);
            b1[nf] = __ldg(eb2 + col + 1);
        }
#pragma unroll
        for (int mf = 0; mf < 2; mf++) {
#pragma unroll
            for (int half = 0; half < 2; half++) {
                int m = mw * 32 + mf * 16 + l4 + half * 8;
                int rcv = s_rcv[m];
                float* orow = edges_out + (size_t)(e0 + m) * EDGE_C;
                float* arow = g_aggr + (size_t)rcv * EDGE_C;
#pragma unroll
                for (int nf = 0; nf < 4; nf++) {
                    int col = nw * 32 + nf * 8 + l2;
                    float o0 = silu_f(c2[mf][nf][half * 2]     + b0[nf]);
                    float o1 = silu_f(c2[mf][nf][half * 2 + 1] + b1[nf]);
                    float2 ov = {o0, o1};
                    *reinterpret_cast<float2*>(orow + col) = ov;
                    atomicAdd(arow + col,     o0);
                    atomicAdd(arow + col + 1, o1);
                }
            }
        }
    }
}

// ---------------------------------------------------------------------------
// Node kernel: 64 nodes / CTA, 256 threads, 2 CTAs/SM (R11 verbatim)
// ---------------------------------------------------------------------------
__global__ __launch_bounds__(256, 2)
void node_mma_kernel(const float* __restrict__ xn,
                     const float* __restrict__ nb1,
                     const float* __restrict__ nb2,
                     float* __restrict__ nodes_out)
{
    extern __shared__ __align__(1024) char dsm[];

    const int tid  = threadIdx.x;
    const int wid  = tid >> 5;
    const int lane = tid & 31;
    const int mw   = wid & 1;
    const int nw   = wid >> 1;
    const int m0   = blockIdx.x * 64;

    const uint32_t sb = smem_u32(dsm);
    const uint32_t la_r  = lane & 15;
    const uint32_t la_kb = (lane >> 4) << 3;
    const uint32_t lb_r  = (lane & 7) | ((lane >> 4) << 3);
    const uint32_t lb_kb = ((lane >> 3) & 1) << 3;

    const int gm = tid >> 2;
    const int gq = tid & 3;
    const int bn = tid >> 1;
    const int bq = tid & 1;
    const size_t grow = (size_t)m0 + gm;
    const bool gvalid = grow < N_NODES;

    {
        const __half* s = g_nW1t + (size_t)bn * 192 + bq * 32;
#pragma unroll
        for (int j = 0; j < 4; j++) {
            uint32_t off = panel_off((uint32_t)bn, (uint32_t)(bq * 32 + j * 8));
            cp16(sb + 8192u + off, s + j * 8);
        }
        CP_COMMIT();
    }
    float4 av[4];
    {
        const float4* rp = reinterpret_cast<const float4*>(xn + grow * NODE_C) + gq * 4;
#pragma unroll
        for (int i = 0; i < 4; i++)
            av[i] = gvalid ? rp[i] : make_float4(0.f, 0.f, 0.f, 0.f);
    }

    float c[2][4][4];
#pragma unroll
    for (int a = 0; a < 2; a++)
#pragma unroll
        for (int b = 0; b < 4; b++)
#pragma unroll
            for (int d = 0; d < 4; d++) c[a][b][d] = 0.f;

#pragma unroll 1
    for (int ch = 0; ch < 3; ch++) {
        __syncthreads();
#pragma unroll
        for (int i = 0; i < 2; i++) {
            uint32_t off = panel_off((uint32_t)gm, (uint32_t)(gq * 16 + i * 8));
            *(uint4*)(dsm + off) = pack8(av[2 * i], av[2 * i + 1]);
        }
        if (ch < 2) {
            const int nc = ch + 1;
            uint32_t dst = 8192u + (uint32_t)((nc & 1) * 16384);
            const __half* s = g_nW1t + (size_t)bn * 192 + nc * 64 + bq * 32;
#pragma unroll
            for (int j = 0; j < 4; j++) {
                uint32_t off = panel_off((uint32_t)bn, (uint32_t)(bq * 32 + j * 8));
                cp16(sb + dst + off, s + j * 8);
            }
            CP_COMMIT();
            const float* rowp = (nc < 2) ? xn + grow * NODE_C + nc * 64
                                         : g_aggr + grow * EDGE_C;
            const float4* rp = reinterpret_cast<const float4*>(rowp) + gq * 4;
#pragma unroll
            for (int i = 0; i < 4; i++)
                av[i] = gvalid ? rp[i] : make_float4(0.f, 0.f, 0.f, 0.f);
        } else {
            // prefetch B2 (nW2t 128x128): p0@40K p1@56K
            const __half* s = g_nW2t + (size_t)bn * 128;
#pragma unroll
            for (int j = 0; j < 8; j++) {
                int seg = bq * 8 + j;
                uint32_t p = (uint32_t)(seg >> 3);
                uint32_t off = p * 16384u + panel_off((uint32_t)bn, (uint32_t)((seg & 7) * 8));
                cp16(sb + 40960u + off, s + seg * 8);
            }
            CP_COMMIT();
        }
        CP_WAIT(1);
        __syncthreads();

        const uint32_t Bp = sb + 8192u + (uint32_t)((ch & 1) * 16384);
#pragma unroll
        for (int ks = 0; ks < 4; ks++) {
            const uint32_t kb = ks * 16;
            uint32_t a4[2][4];
#pragma unroll
            for (int mf = 0; mf < 2; mf++) {
                uint32_t r = (uint32_t)(mw * 32 + mf * 16) + la_r;
                ldsm_x4(a4[mf], sb + panel_off(r, kb + la_kb));
            }
#pragma unroll
            for (int np = 0; np < 2; np++) {
                uint32_t n = (uint32_t)(nw * 32 + np * 16) + lb_r;
                uint32_t b4[4];
                ldsm_x4(b4, Bp + panel_off(n, kb + lb_kb));
#pragma unroll
                for (int mf = 0; mf < 2; mf++) {
                    MMA16816(c[mf][np * 2],     a4[mf], b4);
                    MMA16816(c[mf][np * 2 + 1], a4[mf], b4 + 2);
                }
            }
        }
    }
    __syncthreads();

    // Epilogue1: bias + SiLU -> h fp16
    {
        const int l4 = lane >> 2;
        const int l2 = (lane & 3) * 2;
        const uint32_t hb = (uint32_t)(nw >> 1) * 8192u;   // p0@0, p1@8K
#pragma unroll
        for (int nf = 0; nf < 4; nf++) {
            int col = nw * 32 + nf * 8 + l2;
            float b0 = __ldg(nb1 + col), b1 = __ldg(nb1 + col + 1);
            uint32_t kk = (uint32_t)((nw & 1) * 32 + nf * 8 + l2);
#pragma unroll
            for (int mf = 0; mf < 2; mf++) {
                uint32_t m = (uint32_t)(mw * 32 + mf * 16 + l4);
                float x0 = silu_f(c[mf][nf][0] + b0);
                float x1 = silu_f(c[mf][nf][1] + b1);
                float x2 = silu_f(c[mf][nf][2] + b0);
                float x3 = silu_f(c[mf][nf][3] + b1);
                *(uint32_t*)(dsm + hb + panel_off(m, kk))     = f16x2(x0, x1);
                *(uint32_t*)(dsm + hb + panel_off(m + 8, kk)) = f16x2(x2, x3);
            }
        }
    }
    CP_WAIT(0);
    __syncthreads();

    // GEMM2: h[64,128] @ nW2t^T -> [64,128]
    float c2[2][4][4];
#pragma unroll
    for (int a = 0; a < 2; a++)
#pragma unroll
        for (int b = 0; b < 4; b++)
#pragma unroll
            for (int d = 0; d < 4; d++) c2[a][b][d] = 0.f;

#pragma unroll
    for (int p = 0; p < 2; p++) {
        const uint32_t Ap = sb + (uint32_t)p * 8192u;
        const uint32_t Bp = sb + 40960u + (uint32_t)p * 16384u;
#pragma unroll
        for (int ks = 0; ks < 4; ks++) {
            const uint32_t kb = ks * 16;
            uint32_t a4[2][4];
#pragma unroll
            for (int mf = 0; mf < 2; mf++) {
                uint32_t r = (uint32_t)(mw * 32 + mf * 16) + la_r;
                ldsm_x4(a4[mf], Ap + panel_off(r, kb + la_kb));
            }
#pragma unroll
            for (int np = 0; np < 2; np++) {
                uint32_t n = (uint32_t)(nw * 32 + np * 16) + lb_r;
                uint32_t b4[4];
                ldsm_x4(b4, Bp + panel_off(n, kb + lb_kb));
#pragma unroll
                for (int mf = 0; mf < 2; mf++) {
                    MMA16816(c2[mf][np * 2],     a4[mf], b4);
                    MMA16816(c2[mf][np * 2 + 1], a4[mf], b4 + 2);
                }
            }
        }
    }

    // Epilogue2: + bias, store
    {
        const int l4 = lane >> 2;
        const int l2 = (lane & 3) * 2;
        float b0[4], b1[4];
#pragma unroll
        for (int nf = 0; nf < 4; nf++) {
            int col = nw * 32 + nf * 8 + l2;
            b0[nf] = __ldg(nb2 + col);
            b1[nf] = __ldg(nb2 + col + 1);
        }
#pragma unroll
        for (int mf = 0; mf < 2; mf++) {
#pragma unroll
            for (int half = 0; half < 2; half++) {
                size_t row = (size_t)m0 + mw * 32 + mf * 16 + l4 + half * 8;
                if (row < N_NODES) {
                    float* orow = nodes_out + row * NODE_C;
#pragma unroll
                    for (int nf = 0; nf < 4; nf++) {
                        int col = nw * 32 + nf * 8 + l2;
                        float2 ov;
                        ov.x = c2[mf][nf][half * 2]     + b0[nf];
                        ov.y = c2[mf][nf][half * 2 + 1] + b1[nf];
                        *reinterpret_cast<float2*>(orow + col) = ov;
                    }
                }
            }
        }
    }
}

// ---------------------------------------------------------------------------
extern "C" void kernel_launch(void* const* d_in, const int* in_sizes, int n_in,
                              void* d_out, int out_size)
{
    const float* xn   = (const float*)d_in[0];
    const float* xe   = (const float*)d_in[1];
    const void*  eidx =               d_in[2];
    const float* eW1  = (const float*)d_in[3];
    const float* eb1  = (const float*)d_in[4];
    const float* eW2  = (const float*)d_in[5];
    const float* eb2  = (const float*)d_in[6];
    const float* nW1  = (const float*)d_in[7];
    const float* nb1  = (const float*)d_in[8];
    const float* nW2  = (const float*)d_in[9];
    const float* nb2  = (const float*)d_in[10];

    float* nodes_out = (float*)d_out;
    float* edges_out = (float*)d_out + (size_t)N_NODES * NODE_C;

    cudaFuncSetAttribute(edge_mma_kernel, cudaFuncAttributeMaxDynamicSharedMemorySize, EDGE_SMEM);
    cudaFuncSetAttribute(node_mma_kernel, cudaFuncAttributeMaxDynamicSharedMemorySize, NODE_SMEM);

    prep_kernel<<<9535, 256>>>(xn, eW1, eW2, nW1, nW2);
    edge_mma_kernel<<<N_EDGES / 128, 256, EDGE_SMEM>>>(xe, eidx, eb1, eb2, edges_out);
    node_mma_kernel<<<(N_NODES + 63) / 64, 256, NODE_SMEM>>>(xn, nb1, nb2, nodes_out);
}